// round 4
// baseline (speedup 1.0000x reference)
#include <cuda_runtime.h>

#define N_NODES 10000
#define D       256
#define E_MAX   320000

// ---------------- scratch (no allocations allowed) ----------------
__device__ __align__(16) int   g_deg[N_NODES];
__device__ __align__(16) int   g_row_start[N_NODES + 1];
__device__ __align__(16) int   g_cursor[N_NODES];
__device__ __align__(16) int   g_csr[E_MAX];
__device__ __align__(16) float g_agg[N_NODES * D];
__device__ __align__(16) float g_h1[N_NODES * 256];
__device__ __align__(16) float g_h2[N_NODES * 128];
__device__ __align__(16) float g_h3[N_NODES * 64];
__device__ __align__(16) float g_h4[N_NODES * 32];

// resolve scratch buffers in DEVICE code (host may not query symbol addresses)
__device__ __forceinline__ float* buf_ptr(int sel) {
    switch (sel) {
        case 0: return g_agg;
        case 1: return g_h1;
        case 2: return g_h2;
        case 3: return g_h3;
        case 4: return g_h4;
    }
    return nullptr;
}

// ---------------- CSR build ----------------
__global__ void k_zero_deg() {
    int i = blockIdx.x * blockDim.x + threadIdx.x;
    if (i < N_NODES) g_deg[i] = 0;
}

__global__ void k_hist(const int* __restrict__ dst, int E) {
    int i = blockIdx.x * blockDim.x + threadIdx.x;
    if (i < E) {
        int d = dst[i];
        if ((unsigned)d < (unsigned)N_NODES) atomicAdd(&g_deg[d], 1);
    }
}

__global__ void k_scan() {
    __shared__ int sd[1024];
    __shared__ int carry;
    int t = threadIdx.x;
    if (t == 0) carry = 0;
    __syncthreads();
    for (int base = 0; base < N_NODES; base += 1024) {
        int idx = base + t;
        int v = (idx < N_NODES) ? g_deg[idx] : 0;
        sd[t] = v;
        __syncthreads();
        #pragma unroll
        for (int off = 1; off < 1024; off <<= 1) {
            int tv = (t >= off) ? sd[t - off] : 0;
            __syncthreads();
            sd[t] += tv;
            __syncthreads();
        }
        int incl = sd[t];
        int c = carry;
        __syncthreads();
        if (idx < N_NODES) {
            int ex = c + incl - v;
            g_row_start[idx] = ex;
            g_cursor[idx]    = ex;
        }
        if (t == 1023) carry = c + incl;
        __syncthreads();
    }
    if (t == 0) g_row_start[N_NODES] = carry;
}

__global__ void k_fill(const int* __restrict__ src,
                       const int* __restrict__ dst, int E) {
    int i = blockIdx.x * blockDim.x + threadIdx.x;
    if (i < E) {
        int d = dst[i];
        int s = src[i];
        if ((unsigned)d < (unsigned)N_NODES && (unsigned)s < (unsigned)N_NODES) {
            int pos = atomicAdd(&g_cursor[d], 1);
            g_csr[pos] = s;
        }
    }
}

// ---------------- segment mean (atomic-free gather-sum) ----------------
// one block per node, 64 threads, each thread owns one float4 column chunk
__global__ void __launch_bounds__(64) k_aggregate(const float* __restrict__ x) {
    int n = blockIdx.x;
    int t = threadIdx.x;
    int s = g_row_start[n];
    int e = g_row_start[n + 1];
    const float4* x4 = (const float4*)x;

    float4 a0 = make_float4(0.f, 0.f, 0.f, 0.f);
    float4 a1 = a0, a2 = a0, a3 = a0;

    int i = s;
    for (; i + 4 <= e; i += 4) {
        int s0 = g_csr[i], s1 = g_csr[i + 1], s2 = g_csr[i + 2], s3 = g_csr[i + 3];
        float4 v0 = x4[s0 * 64 + t];
        float4 v1 = x4[s1 * 64 + t];
        float4 v2 = x4[s2 * 64 + t];
        float4 v3 = x4[s3 * 64 + t];
        a0.x += v0.x; a0.y += v0.y; a0.z += v0.z; a0.w += v0.w;
        a1.x += v1.x; a1.y += v1.y; a1.z += v1.z; a1.w += v1.w;
        a2.x += v2.x; a2.y += v2.y; a2.z += v2.z; a2.w += v2.w;
        a3.x += v3.x; a3.y += v3.y; a3.z += v3.z; a3.w += v3.w;
    }
    for (; i < e; i++) {
        int s0 = g_csr[i];
        float4 v0 = x4[s0 * 64 + t];
        a0.x += v0.x; a0.y += v0.y; a0.z += v0.z; a0.w += v0.w;
    }

    int deg = e - s;
    float inv = 1.0f / (float)(deg > 1 ? deg : 1);
    float4 r;
    r.x = (a0.x + a1.x + a2.x + a3.x) * inv;
    r.y = (a0.y + a1.y + a2.y + a3.y) * inv;
    r.z = (a0.z + a1.z + a2.z + a3.z) * inv;
    r.w = (a0.w + a1.w + a2.w + a3.w) * inv;
    ((float4*)g_agg)[n * 64 + t] = r;
}

// ---------------- tiled SGEMM: C = act(bias + A0@W0^T [+ A1@W1^T]) ----------------
// A selected by selA0 (scratch buffer) or external pointer; second pass external
// W: [N,K] row-major (K-contiguous)
// BM=BN=64, BK=16, 256 threads, 4x4 micro-tile per thread
template <bool RELU>
__global__ void __launch_bounds__(256)
k_gemm(int selA0, const float* __restrict__ A0ext,
       const float* __restrict__ W0, int K0,
       const float* __restrict__ A1ext, const float* __restrict__ W1, int K1,
       const float* __restrict__ bias, int selC,
       int M, int N) {
    const int BM = 64, BN = 64, BK = 16;
    __shared__ float As[BK][BM];
    __shared__ float Bs[BK][BN];

    int tid = threadIdx.x;
    int tx = tid & 15;         // 0..15 -> 4 cols each
    int ty = tid >> 4;         // 0..15 -> 4 rows each
    int bm = blockIdx.y * BM;
    int bn = blockIdx.x * BN;

    int lr = tid >> 2;         // 0..63: tile row for loading
    int lk = (tid & 3) * 4;    // 0,4,8,12: k offset (float4)

    const float* A0 = (selA0 >= 0) ? buf_ptr(selA0) : A0ext;
    float* C = buf_ptr(selC);

    float acc[4][4] = {};

    #pragma unroll
    for (int pass = 0; pass < 2; pass++) {
        const float* A = pass ? A1ext : A0;
        const float* W = pass ? W1 : W0;
        int K = pass ? K1 : K0;
        if (A == nullptr) continue;

        for (int kk = 0; kk < K; kk += BK) {
            // load A tile (transpose k into rows of As)
            int gm = bm + lr;
            float4 av = make_float4(0.f, 0.f, 0.f, 0.f);
            if (gm < M) av = *(const float4*)(A + (size_t)gm * K + kk + lk);
            As[lk + 0][lr] = av.x;
            As[lk + 1][lr] = av.y;
            As[lk + 2][lr] = av.z;
            As[lk + 3][lr] = av.w;
            // load W tile
            int gn = bn + lr;
            float4 bv = make_float4(0.f, 0.f, 0.f, 0.f);
            if (gn < N) bv = *(const float4*)(W + (size_t)gn * K + kk + lk);
            Bs[lk + 0][lr] = bv.x;
            Bs[lk + 1][lr] = bv.y;
            Bs[lk + 2][lr] = bv.z;
            Bs[lk + 3][lr] = bv.w;
            __syncthreads();

            #pragma unroll
            for (int k = 0; k < BK; k++) {
                float4 a = *(const float4*)&As[k][ty * 4];
                float4 b = *(const float4*)&Bs[k][tx * 4];
                acc[0][0] += a.x * b.x; acc[0][1] += a.x * b.y; acc[0][2] += a.x * b.z; acc[0][3] += a.x * b.w;
                acc[1][0] += a.y * b.x; acc[1][1] += a.y * b.y; acc[1][2] += a.y * b.z; acc[1][3] += a.y * b.w;
                acc[2][0] += a.z * b.x; acc[2][1] += a.z * b.y; acc[2][2] += a.z * b.z; acc[2][3] += a.z * b.w;
                acc[3][0] += a.w * b.x; acc[3][1] += a.w * b.y; acc[3][2] += a.w * b.z; acc[3][3] += a.w * b.w;
            }
            __syncthreads();
        }
    }

    // epilogue: bias + optional relu
    #pragma unroll
    for (int i = 0; i < 4; i++) {
        int m = bm + ty * 4 + i;
        if (m >= M) continue;
        #pragma unroll
        for (int j = 0; j < 4; j++) {
            int n = bn + tx * 4 + j;
            if (n >= N) continue;
            float v = acc[i][j] + bias[n];
            if (RELU) v = fmaxf(v, 0.f);
            C[(size_t)m * N + n] = v;
        }
    }
}

// ---------------- final 32 -> 3 layer ----------------
__global__ void k_final(const float* __restrict__ W3, const float* __restrict__ b3,
                        float* __restrict__ out, int M) {
    __shared__ float w[96];
    __shared__ float b[3];
    int t = threadIdx.x;
    if (t < 96) w[t] = W3[t];
    if (t < 3)  b[t] = b3[t];
    __syncthreads();
    int idx = blockIdx.x * blockDim.x + t;
    if (idx < M * 3) {
        int m = idx / 3;
        int j = idx - m * 3;
        const float* h = g_h4 + m * 32;
        float s = b[j];
        #pragma unroll
        for (int k = 0; k < 32; k++) s += h[k] * w[j * 32 + k];
        out[idx] = s;
    }
}

// ---------------- launch ----------------
extern "C" void kernel_launch(void* const* d_in, const int* in_sizes, int n_in,
                              void* d_out, int out_size) {
    const float* x   = (const float*)d_in[0];
    const int*   ei  = (const int*)d_in[1];     // int32 (harness dtype contract)
    const float* W_l = (const float*)d_in[2];
    const float* b_l = (const float*)d_in[3];
    const float* W_r = (const float*)d_in[4];
    const float* Wa  = (const float*)d_in[5];
    const float* ba  = (const float*)d_in[6];
    const float* W1  = (const float*)d_in[7];
    const float* b1  = (const float*)d_in[8];
    const float* W2  = (const float*)d_in[9];
    const float* b2  = (const float*)d_in[10];
    const float* W3  = (const float*)d_in[11];
    const float* b3  = (const float*)d_in[12];
    float*       out = (float*)d_out;

    int E = in_sizes[1] / 2;
    const int* src = ei;
    const int* dst = ei + E;

    // CSR build
    k_zero_deg<<<(N_NODES + 255) / 256, 256>>>();
    k_hist<<<(E + 255) / 256, 256>>>(dst, E);
    k_scan<<<1, 1024>>>();
    k_fill<<<(E + 255) / 256, 256>>>(src, dst, E);

    // segment mean -> g_agg (sel 0)
    k_aggregate<<<N_NODES, 64>>>(x);

    // layer 1: h1 = relu(agg@W_l^T + x@W_r^T + b_l)   M=10000, N=256, K=256+256
    {
        dim3 grid(256 / 64, (N_NODES + 63) / 64);
        k_gemm<true><<<grid, 256>>>(0, nullptr, W_l, 256, x, W_r, 256, b_l, 1, N_NODES, 256);
    }
    // layer 2: h2 = relu(h1@Wa^T + ba)   N=128, K=256
    {
        dim3 grid(128 / 64, (N_NODES + 63) / 64);
        k_gemm<true><<<grid, 256>>>(1, nullptr, Wa, 256, nullptr, nullptr, 0, ba, 2, N_NODES, 128);
    }
    // layer 3: h3 = relu(h2@W1^T + b1)   N=64, K=128
    {
        dim3 grid(1, (N_NODES + 63) / 64);
        k_gemm<true><<<grid, 256>>>(2, nullptr, W1, 128, nullptr, nullptr, 0, b1, 3, N_NODES, 64);
    }
    // layer 4: h4 = relu(h3@W2^T + b2)   N=32, K=64
    {
        dim3 grid(1, (N_NODES + 63) / 64);
        k_gemm<true><<<grid, 256>>>(3, nullptr, W2, 64, nullptr, nullptr, 0, b2, 4, N_NODES, 32);
    }
    // final: out = h4@W3^T + b3   N=3, K=32
    k_final<<<(N_NODES * 3 + 255) / 256, 256>>>(W3, b3, out, N_NODES);
}